// round 16
// baseline (speedup 1.0000x reference)
#include <cuda_runtime.h>
#include <cuda_bf16.h>
#include <cuda_fp16.h>
#include <math.h>
#include <stdint.h>

// ---------------------------------------------------------------------------
// RGCN 2-layer, gather-side restructuring + dst-sorted segmented reduction.
// HARD RULE (empirical): __device__ globals must NEVER be referenced from
// host code; they are bound inside __global__ wrappers in device code only.
//
//   perm = edges sorted by dst (counting sort, once, reused by both layers)
//   xsplit = bf16-hi/lo(x)
//   [h1 | xw16] = x @ [root1 | W1cat] (+b1)  (bf16x3 mma GEMM; xw fp16)
//   h1[d] += sum_{e in seg(d)} xw16[src_e, r_e] * inv[r_e,d]   (NO atomics)
//   hsplit = bf16-hi/lo(relu(h1))
//   [oacc | hw] = relu(h1) @ [root2 | W2cat] (+b2)  (oacc -> g_cnt storage)
//   oacc[d] += segmented sum of hw messages                      (NO atomics)
//   d_out = log_softmax(relu(oacc))          (plain stores, k_final only)
//
// g_agg float-index map:
//   [0, 51.2M)    xw fp16 (layer1) / hw fp32 (layer2, [0,25.6M))
//   [51.2M,57.6M) pre-split A (uint2 hi/lo pairs, 32/row)
//   [60M, ...)    perm int[E];  62M cnt_dst;  63M off;  64M fill;  65M bsum
// ---------------------------------------------------------------------------

namespace {
constexpr int N_NODES = 100000;
constexpr int R = 16;
constexpr int D = 64;
constexpr int KBIG = R * D;  // 1024
constexpr int SEGS = 128;    // row-segments per column block
}

__device__ int   g_cnt[R * N_NODES];
__device__ float g_inv[R * N_NODES];
__device__ float g_agg[(size_t)N_NODES * KBIG];
__device__ float g_h1[(size_t)N_NODES * D];

// Device-side region binding (never referenced from host).
__device__ __forceinline__ uint2* axs_ptr()  { return reinterpret_cast<uint2*>(g_agg) + (size_t)N_NODES * 256; }
__device__ __forceinline__ int*   perm_ptr() { return reinterpret_cast<int*>(g_agg) + 60000000; }
__device__ __forceinline__ int*   cntd_ptr() { return reinterpret_cast<int*>(g_agg) + 62000000; }
__device__ __forceinline__ int*   off_ptr()  { return reinterpret_cast<int*>(g_agg) + 63000000; }
__device__ __forceinline__ int*   fill_ptr() { return reinterpret_cast<int*>(g_agg) + 64000000; }
__device__ __forceinline__ int*   bsum_ptr() { return reinterpret_cast<int*>(g_agg) + 65000000; }

// ---------------------------------------------------------------------------
__global__ void k_zero_cnt() {
    int i = blockIdx.x * blockDim.x + threadIdx.x;
    if (i < R * N_NODES) g_cnt[i] = 0;
}
__global__ void k_count(const int* __restrict__ dst, const int* __restrict__ et, int E) {
    int i = blockIdx.x * blockDim.x + threadIdx.x;
    if (i < E) atomicAdd(&g_cnt[et[i] * N_NODES + dst[i]], 1);
}
__global__ void k_inv() {
    int i = blockIdx.x * blockDim.x + threadIdx.x;
    if (i < R * N_NODES) {
        int c = g_cnt[i];
        g_inv[i] = 1.0f / (float)(c > 0 ? c : 1);
    }
}

// ---- dst counting sort -----------------------------------------------------
__global__ void k_zero_dst() {
    int i = blockIdx.x * blockDim.x + threadIdx.x;
    if (i < N_NODES) { cntd_ptr()[i] = 0; fill_ptr()[i] = 0; }
}
__global__ void k_count_dst(const int* __restrict__ dst, int E) {
    int i = blockIdx.x * blockDim.x + threadIdx.x;
    if (i < E) atomicAdd(&cntd_ptr()[dst[i]], 1);
}
__global__ void k_scan1() {
    __shared__ int sm[256];
    int tid = threadIdx.x;
    int d = blockIdx.x * 256 + tid;
    int v = (d < N_NODES) ? cntd_ptr()[d] : 0;
    sm[tid] = v; __syncthreads();
    for (int ofs = 1; ofs < 256; ofs <<= 1) {
        int t = (tid >= ofs) ? sm[tid - ofs] : 0;
        __syncthreads();
        sm[tid] += t;
        __syncthreads();
    }
    if (d < N_NODES) off_ptr()[d] = sm[tid] - v;
    if (tid == 255) bsum_ptr()[blockIdx.x] = sm[255];
}
__global__ void k_scan2(int nb) {
    __shared__ int sm[512];
    int tid = threadIdx.x;
    int v = (tid < nb) ? bsum_ptr()[tid] : 0;
    sm[tid] = v; __syncthreads();
    for (int ofs = 1; ofs < 512; ofs <<= 1) {
        int t = (tid >= ofs) ? sm[tid - ofs] : 0;
        __syncthreads();
        sm[tid] += t;
        __syncthreads();
    }
    if (tid < nb) bsum_ptr()[tid] = sm[tid] - v;   // exclusive
}
__global__ void k_scan3() {
    int d = blockIdx.x * blockDim.x + threadIdx.x;
    if (d < N_NODES) off_ptr()[d] += bsum_ptr()[d >> 8];
}
__global__ void k_place(const int* __restrict__ dst, int E) {
    int e = blockIdx.x * blockDim.x + threadIdx.x;
    if (e >= E) return;
    int d = dst[e];
    int pos = off_ptr()[d] + atomicAdd(&fill_ptr()[d], 1);
    perm_ptr()[pos] = e;
}

// ---------------------------------------------------------------------------
// bf16 helpers: pack (x,y) into bf16x2 hi word + residual lo word.
// ---------------------------------------------------------------------------
__device__ __forceinline__ uint32_t bf2_split(float x, float y, uint32_t& lo_out) {
    __nv_bfloat162 h = __floats2bfloat162_rn(x, y);
    float2 hf = __bfloat1622float2(h);
    __nv_bfloat162 l = __floats2bfloat162_rn(x - hf.x, y - hf.y);
    lo_out = *reinterpret_cast<uint32_t*>(&l);
    return *reinterpret_cast<uint32_t*>(&h);
}

__device__ __forceinline__ void mma_bf16(float* c, const uint32_t* a, const uint32_t* b) {
    asm volatile(
        "mma.sync.aligned.m16n8k16.row.col.f32.bf16.bf16.f32 "
        "{%0,%1,%2,%3}, {%4,%5,%6,%7}, {%8,%9}, {%0,%1,%2,%3};"
        : "+f"(c[0]), "+f"(c[1]), "+f"(c[2]), "+f"(c[3])
        : "r"(a[0]), "r"(a[1]), "r"(a[2]), "r"(a[3]), "r"(b[0]), "r"(b[1]));
}

// ---------------------------------------------------------------------------
// Pre-split kernels: A rows -> packed uint2{hi,lo} pairs (32 per row).
// ---------------------------------------------------------------------------
__global__ void k_split_x(const float* __restrict__ x) {
    int i = blockIdx.x * blockDim.x + threadIdx.x;
    if (i >= N_NODES * 16) return;
    float4 v = reinterpret_cast<const float4*>(x)[i];
    uint32_t l01, l23;
    uint32_t h01 = bf2_split(v.x, v.y, l01);
    uint32_t h23 = bf2_split(v.z, v.w, l23);
    int row = i >> 4, c4 = i & 15;
    *reinterpret_cast<uint4*>(&axs_ptr()[(size_t)row * 32 + 2 * c4]) =
        make_uint4(h01, l01, h23, l23);
}

__global__ void k_split_h1() {
    int i = blockIdx.x * blockDim.x + threadIdx.x;
    if (i >= N_NODES * 16) return;
    float4 v = reinterpret_cast<const float4*>(g_h1)[i];
    v.x = fmaxf(v.x, 0.f); v.y = fmaxf(v.y, 0.f);
    v.z = fmaxf(v.z, 0.f); v.w = fmaxf(v.w, 0.f);
    uint32_t l01, l23;
    uint32_t h01 = bf2_split(v.x, v.y, l01);
    uint32_t h23 = bf2_split(v.z, v.w, l23);
    int row = i >> 4, c4 = i & 15;
    *reinterpret_cast<uint4*>(&axs_ptr()[(size_t)row * 32 + 2 * c4]) =
        make_uint4(h01, l01, h23, l23);
}

// ---------------------------------------------------------------------------
// Persistent fused GEMM body (A pre-split) — identical to R15-verified code.
// ---------------------------------------------------------------------------
namespace {
constexpr int SP = 36;
}

__device__ __forceinline__ void gemm_body(
    const uint2* __restrict__ Aps, const float* __restrict__ root,
    const float* __restrict__ W, const float* __restrict__ bias,
    float* __restrict__ outRoot, float* __restrict__ outWf,
    __half* __restrict__ outWh,
    int d1, int d2, int dout, int halfW, int rowBlocks) {
    __shared__ uint2 Ax[64 * SP];
    __shared__ uint2 Bx[64 * SP];

    const int tid = threadIdx.x;
    const int NC = (d1 + d2 + 63) / 64;
    const int cb = blockIdx.x % NC;
    const int seg = blockIdx.x / NC;
    const int dtot = d1 + d2;

#pragma unroll
    for (int i = 0; i < 8; ++i) {
        int idx = tid + i * 256;
        int p = idx >> 6, c = idx & 63;
        int gc = cb * 64 + c;
        int k0 = p * 2;
        float f0 = 0.f, f1 = 0.f;
        if (gc < d1) {
            f0 = root[(size_t)k0 * d1 + gc];
            f1 = root[(size_t)(k0 + 1) * d1 + gc];
        } else if (gc < dtot) {
            int w = gc - d1;
            int r = w / dout, j = w - r * dout;
            f0 = W[((size_t)r * 64 + k0) * dout + j];
            f1 = W[((size_t)r * 64 + k0 + 1) * dout + j];
        }
        uint32_t lo;
        uint32_t hi = bf2_split(f0, f1, lo);
        Bx[c * SP + p] = make_uint2(hi, lo);
    }

    const int wid = tid >> 5, lane = tid & 31;
    const int g = lane >> 2, tg = lane & 3;
    const int wm = (wid & 3) * 16;
    const int wn = (wid >> 2) * 32;
    const int arow = tid >> 4, ac4 = tid & 15;

    uint4 pref[4];
    {
        int rb = seg;
#pragma unroll
        for (int i = 0; i < 4; ++i) {
            int grow = rb * 64 + arow + i * 16;
            pref[i] = make_uint4(0u, 0u, 0u, 0u);
            if (rb < rowBlocks && grow < N_NODES)
                pref[i] = *reinterpret_cast<const uint4*>(
                    &Aps[(size_t)grow * 32 + 2 * ac4]);
        }
    }

    for (int rb = seg; rb < rowBlocks; rb += SEGS) {
#pragma unroll
        for (int i = 0; i < 4; ++i)
            *reinterpret_cast<uint4*>(&Ax[(arow + i * 16) * SP + 2 * ac4]) = pref[i];
        __syncthreads();

        {
            int rbn = rb + SEGS;
#pragma unroll
            for (int i = 0; i < 4; ++i) {
                int grow = rbn * 64 + arow + i * 16;
                uint4 v = make_uint4(0u, 0u, 0u, 0u);
                if (rbn < rowBlocks && grow < N_NODES)
                    v = *reinterpret_cast<const uint4*>(
                        &Aps[(size_t)grow * 32 + 2 * ac4]);
                pref[i] = v;
            }
        }

        float acc[4][4];
#pragma unroll
        for (int nt = 0; nt < 4; ++nt)
#pragma unroll
            for (int q = 0; q < 4; ++q) acc[nt][q] = 0.f;

#pragma unroll
        for (int ks = 0; ks < 4; ++ks) {
            const int p0 = ks * 8;
            uint2 A0 = Ax[(wm + g)     * SP + p0 + tg];
            uint2 A1 = Ax[(wm + g + 8) * SP + p0 + tg];
            uint2 A2 = Ax[(wm + g)     * SP + p0 + tg + 4];
            uint2 A3 = Ax[(wm + g + 8) * SP + p0 + tg + 4];
            uint32_t ah[4] = {A0.x, A1.x, A2.x, A3.x};
            uint32_t al[4] = {A0.y, A1.y, A2.y, A3.y};
            uint32_t bh[4][2], bl[4][2];
#pragma unroll
            for (int nt = 0; nt < 4; ++nt) {
                int c0 = wn + nt * 8 + g;
                uint2 B0 = Bx[c0 * SP + p0 + tg];
                uint2 B1 = Bx[c0 * SP + p0 + tg + 4];
                bh[nt][0] = B0.x; bh[nt][1] = B1.x;
                bl[nt][0] = B0.y; bl[nt][1] = B1.y;
            }
#pragma unroll
            for (int nt = 0; nt < 4; ++nt) {
                mma_bf16(acc[nt], ah, bh[nt]);
                mma_bf16(acc[nt], ah, bl[nt]);
                mma_bf16(acc[nt], al, bh[nt]);
            }
        }

#pragma unroll
        for (int nt = 0; nt < 4; ++nt) {
            int col = wn + nt * 8 + 2 * tg;
            int gc = cb * 64 + col;
            int r0 = rb * 64 + wm + g;
            int r1 = r0 + 8;
            float2 v0 = make_float2(acc[nt][0], acc[nt][1]);
            float2 v1 = make_float2(acc[nt][2], acc[nt][3]);
            if (gc < d1) {
                float bx = bias[gc], by = bias[gc + 1];
                v0.x += bx; v0.y += by; v1.x += bx; v1.y += by;
                if (r0 < N_NODES)
                    *reinterpret_cast<float2*>(&outRoot[(size_t)r0 * d1 + gc]) = v0;
                if (r1 < N_NODES)
                    *reinterpret_cast<float2*>(&outRoot[(size_t)r1 * d1 + gc]) = v1;
            } else if (gc < dtot) {
                int w = gc - d1;
                if (halfW) {
                    if (r0 < N_NODES)
                        *reinterpret_cast<__half2*>(&outWh[(size_t)r0 * d2 + w]) =
                            __floats2half2_rn(v0.x, v0.y);
                    if (r1 < N_NODES)
                        *reinterpret_cast<__half2*>(&outWh[(size_t)r1 * d2 + w]) =
                            __floats2half2_rn(v1.x, v1.y);
                } else {
                    if (r0 < N_NODES)
                        *reinterpret_cast<float2*>(&outWf[(size_t)r0 * d2 + w]) = v0;
                    if (r1 < N_NODES)
                        *reinterpret_cast<float2*>(&outWf[(size_t)r1 * d2 + w]) = v1;
                }
            }
        }
        __syncthreads();
    }
}

__global__ void __launch_bounds__(256) k_gemm_l1(
    const float* __restrict__ W1, const float* __restrict__ root1,
    const float* __restrict__ b1, int rowBlocks) {
    gemm_body(axs_ptr(), root1, W1, b1, g_h1, nullptr,
              reinterpret_cast<__half*>(g_agg), 64, 1024, 64, 1, rowBlocks);
}

__global__ void __launch_bounds__(256) k_gemm_l2(
    const float* __restrict__ W2, const float* __restrict__ root2,
    const float* __restrict__ b2, int rowBlocks) {
    gemm_body(axs_ptr(), root2, W2, b2, reinterpret_cast<float*>(g_cnt),
              g_agg, nullptr, 16, 256, 16, 0, rowBlocks);
}

// ---------------------------------------------------------------------------
// Segmented gather-reduce (no atomics). Warp per dst; lane owns 2 columns.
// h1[d] already holds the root term; add the message sum with plain stores.
// ---------------------------------------------------------------------------
__global__ void k_gather1(const int* __restrict__ src, const int* __restrict__ et) {
    int gw = (int)((blockIdx.x * (size_t)blockDim.x + threadIdx.x) >> 5);
    int lane = threadIdx.x & 31;
    if (gw >= N_NODES) return;
    int d = gw;
    int start = off_ptr()[d];
    int n = cntd_ptr()[d];
    const __half* xwh = reinterpret_cast<const __half*>(g_agg);
    float2 acc = make_float2(0.f, 0.f);
    for (int j = 0; j < n; ++j) {
        int eid = perm_ptr()[start + j];
        int s = __ldg(src + eid);
        int r = __ldg(et + eid);
        float w = g_inv[r * N_NODES + d];
        uint32_t raw = *reinterpret_cast<const uint32_t*>(
            &xwh[(size_t)s * 1024 + r * 64 + lane * 2]);
        float2 f = __half22float2(*reinterpret_cast<__half2*>(&raw));
        acc.x += w * f.x;
        acc.y += w * f.y;
    }
    float2* hp = reinterpret_cast<float2*>(&g_h1[(size_t)d * D + lane * 2]);
    float2 cur = *hp;
    cur.x += acc.x; cur.y += acc.y;
    *hp = cur;
}

// 4 threads per dst; each owns a float4 of the 16 outputs.
__global__ void k_gather2(const int* __restrict__ src, const int* __restrict__ et) {
    int t = blockIdx.x * blockDim.x + threadIdx.x;
    int d = t >> 2, q = t & 3;
    if (d >= N_NODES) return;
    int start = off_ptr()[d];
    int n = cntd_ptr()[d];
    float4 acc = make_float4(0.f, 0.f, 0.f, 0.f);
    for (int j = 0; j < n; ++j) {
        int eid = perm_ptr()[start + j];
        int s = __ldg(src + eid);
        int r = __ldg(et + eid);
        float w = g_inv[r * N_NODES + d];
        float4 v = *reinterpret_cast<const float4*>(
            &g_agg[(size_t)s * 256 + r * 16 + q * 4]);
        acc.x += w * v.x; acc.y += w * v.y;
        acc.z += w * v.z; acc.w += w * v.w;
    }
    float* oacc = reinterpret_cast<float*>(g_cnt);
    float4* op = reinterpret_cast<float4*>(&oacc[(size_t)d * 16 + q * 4]);
    float4 cur = *op;
    cur.x += acc.x; cur.y += acc.y; cur.z += acc.z; cur.w += acc.w;
    *op = cur;
}

// relu + log_softmax over 16 classes; reads oacc (g_cnt storage), writes d_out
// with plain stores only. One thread per row.
__global__ void k_final(float* __restrict__ out) {
    int row = blockIdx.x * blockDim.x + threadIdx.x;
    if (row >= N_NODES) return;
    float v[16];
    const float4* p = reinterpret_cast<const float4*>(
        &reinterpret_cast<const float*>(g_cnt)[(size_t)row * 16]);
#pragma unroll
    for (int q = 0; q < 4; ++q) {
        float4 t = p[q];
        v[q * 4 + 0] = fmaxf(t.x, 0.f);
        v[q * 4 + 1] = fmaxf(t.y, 0.f);
        v[q * 4 + 2] = fmaxf(t.z, 0.f);
        v[q * 4 + 3] = fmaxf(t.w, 0.f);
    }
    float m = -1e30f;
#pragma unroll
    for (int j = 0; j < 16; ++j) m = fmaxf(m, v[j]);
    float s = 0.f;
#pragma unroll
    for (int j = 0; j < 16; ++j) s += expf(v[j] - m);
    float ls = m + logf(s);
    float4* q4 = reinterpret_cast<float4*>(&out[(size_t)row * 16]);
#pragma unroll
    for (int q = 0; q < 4; ++q)
        q4[q] = make_float4(v[q * 4 + 0] - ls, v[q * 4 + 1] - ls,
                            v[q * 4 + 2] - ls, v[q * 4 + 3] - ls);
}

// ---------------------------------------------------------------------------
extern "C" void kernel_launch(void* const* d_in, const int* in_sizes, int n_in,
                              void* d_out, int out_size) {
    const float* x     = (const float*)d_in[0];
    const int*   ei    = (const int*)d_in[1];
    const int*   et    = (const int*)d_in[2];
    const float* W1    = (const float*)d_in[3];
    const float* root1 = (const float*)d_in[4];
    const float* b1    = (const float*)d_in[5];
    const float* W2    = (const float*)d_in[6];
    const float* root2 = (const float*)d_in[7];
    const float* b2    = (const float*)d_in[8];
    float* out = (float*)d_out;

    const int E = in_sizes[2];
    const int* src = ei;
    const int* dst = ei + E;

    const int t = 256;
    const int gRN = (R * N_NODES + t - 1) / t;
    const int gN  = (N_NODES + t - 1) / t;
    const int gE  = (E + t - 1) / t;
    const int rowBlocks = (N_NODES + 63) / 64;
    const int gSplit = (N_NODES * 16 + t - 1) / t;
    const int scanBlocks = (N_NODES + 255) / 256;   // 391
    const int gG1 = (int)(((size_t)N_NODES * 32 + t - 1) / t);
    const int gG2 = (N_NODES * 4 + t - 1) / t;

    // per-(r,dst) counts + inverse (g_cnt is dead after k_inv)
    k_zero_cnt<<<gRN, t>>>();
    k_count<<<gE, t>>>(dst, et, E);
    k_inv<<<gRN, t>>>();

    // dst counting sort (perm reused by both layers)
    k_zero_dst<<<gN, t>>>();
    k_count_dst<<<gE, t>>>(dst, E);
    k_scan1<<<scanBlocks, 256>>>();
    k_scan2<<<1, 512>>>(scanBlocks);
    k_scan3<<<gN, t>>>();
    k_place<<<gE, t>>>(dst, E);

    // layer 1: pre-split x, GEMM, segmented gather into h1
    k_split_x<<<gSplit, t>>>(x);
    k_gemm_l1<<<17 * SEGS, t>>>(W1, root1, b1, rowBlocks);
    k_gather1<<<gG1, t>>>(src, et);

    // layer 2: pre-split relu(h1), GEMM (oacc in g_cnt, hw fp32), gather, final
    k_split_h1<<<gSplit, t>>>();
    k_gemm_l2<<<5 * SEGS, t>>>(W2, root2, b2, rowBlocks);
    k_gather2<<<gG2, t>>>(src, et);
    k_final<<<gN, t>>>(out);
}

// round 17
// speedup vs baseline: 1.1590x; 1.1590x over previous
#include <cuda_runtime.h>
#include <cuda_bf16.h>
#include <cuda_fp16.h>
#include <math.h>
#include <stdint.h>

// ---------------------------------------------------------------------------
// RGCN 2-layer, gather-side restructuring + dst-sorted run-compacted scatter.
// HARD RULE (empirical): __device__ globals must NEVER be referenced from
// host code; they are bound inside __global__ wrappers in device code only.
//
//   sorted triples (ssrc,sret,sdst) = edges counting-sorted by dst (once)
//   xsplit = bf16-hi/lo(x)
//   [h1 | xw16] = x @ [root1 | W1cat] (+b1)  (bf16x3 mma GEMM; xw fp16)
//   h1[d] += run-compacted RED of xw16[src,r]*inv[r,d] over sorted edges
//   hsplit = bf16-hi/lo(relu(h1))
//   [oacc | hw] = relu(h1) @ [root2 | W2cat] (+b2)  (oacc -> g_cnt storage)
//   oacc[d] += run-compacted RED of hw messages
//   d_out = log_softmax(relu(oacc))          (plain stores, k_final only)
//
// g_agg float-index map:
//   [0, 51.2M)    xw fp16 (layer1) / hw fp32 (layer2, [0,25.6M))
//   [51.2M,57.6M) pre-split A (uint2 hi/lo pairs, 32/row)
//   60M ssrc[E]; 62M sret[E]; 64M sdst[E]; 66M cntd; 67M off; 68M fill; 69M bsum
// ---------------------------------------------------------------------------

namespace {
constexpr int N_NODES = 100000;
constexpr int R = 16;
constexpr int D = 64;
constexpr int KBIG = R * D;  // 1024
constexpr int SEGS = 128;    // row-segments per column block
constexpr int CH = 16;       // sorted-edge chunk per scatter thread
}

__device__ int   g_cnt[R * N_NODES];
__device__ float g_inv[R * N_NODES];
__device__ float g_agg[(size_t)N_NODES * KBIG];
__device__ float g_h1[(size_t)N_NODES * D];

// Device-side region binding (never referenced from host).
__device__ __forceinline__ uint2* axs_ptr()  { return reinterpret_cast<uint2*>(g_agg) + (size_t)N_NODES * 256; }
__device__ __forceinline__ int*   ssrc_ptr() { return reinterpret_cast<int*>(g_agg) + 60000000; }
__device__ __forceinline__ int*   sret_ptr() { return reinterpret_cast<int*>(g_agg) + 62000000; }
__device__ __forceinline__ int*   sdst_ptr() { return reinterpret_cast<int*>(g_agg) + 64000000; }
__device__ __forceinline__ int*   cntd_ptr() { return reinterpret_cast<int*>(g_agg) + 66000000; }
__device__ __forceinline__ int*   off_ptr()  { return reinterpret_cast<int*>(g_agg) + 67000000; }
__device__ __forceinline__ int*   fill_ptr() { return reinterpret_cast<int*>(g_agg) + 68000000; }
__device__ __forceinline__ int*   bsum_ptr() { return reinterpret_cast<int*>(g_agg) + 69000000; }

// ---------------------------------------------------------------------------
__global__ void k_zero_cnt() {
    int i = blockIdx.x * blockDim.x + threadIdx.x;
    if (i < R * N_NODES) g_cnt[i] = 0;
}
__global__ void k_count(const int* __restrict__ dst, const int* __restrict__ et, int E) {
    int i = blockIdx.x * blockDim.x + threadIdx.x;
    if (i < E) atomicAdd(&g_cnt[et[i] * N_NODES + dst[i]], 1);
}
__global__ void k_inv() {
    int i = blockIdx.x * blockDim.x + threadIdx.x;
    if (i < R * N_NODES) {
        int c = g_cnt[i];
        g_inv[i] = 1.0f / (float)(c > 0 ? c : 1);
    }
}

// ---- dst counting sort -> sorted triples ----------------------------------
__global__ void k_zero_dst() {
    int i = blockIdx.x * blockDim.x + threadIdx.x;
    if (i < N_NODES) { cntd_ptr()[i] = 0; fill_ptr()[i] = 0; }
}
__global__ void k_count_dst(const int* __restrict__ dst, int E) {
    int i = blockIdx.x * blockDim.x + threadIdx.x;
    if (i < E) atomicAdd(&cntd_ptr()[dst[i]], 1);
}
__global__ void k_scan1() {
    __shared__ int sm[256];
    int tid = threadIdx.x;
    int d = blockIdx.x * 256 + tid;
    int v = (d < N_NODES) ? cntd_ptr()[d] : 0;
    sm[tid] = v; __syncthreads();
    for (int ofs = 1; ofs < 256; ofs <<= 1) {
        int t = (tid >= ofs) ? sm[tid - ofs] : 0;
        __syncthreads();
        sm[tid] += t;
        __syncthreads();
    }
    if (d < N_NODES) off_ptr()[d] = sm[tid] - v;
    if (tid == 255) bsum_ptr()[blockIdx.x] = sm[255];
}
__global__ void k_scan2(int nb) {
    __shared__ int sm[512];
    int tid = threadIdx.x;
    int v = (tid < nb) ? bsum_ptr()[tid] : 0;
    sm[tid] = v; __syncthreads();
    for (int ofs = 1; ofs < 512; ofs <<= 1) {
        int t = (tid >= ofs) ? sm[tid - ofs] : 0;
        __syncthreads();
        sm[tid] += t;
        __syncthreads();
    }
    if (tid < nb) bsum_ptr()[tid] = sm[tid] - v;   // exclusive
}
__global__ void k_scan3() {
    int d = blockIdx.x * blockDim.x + threadIdx.x;
    if (d < N_NODES) off_ptr()[d] += bsum_ptr()[d >> 8];
}
__global__ void k_place(const int* __restrict__ src, const int* __restrict__ dst,
                        const int* __restrict__ et, int E) {
    int e = blockIdx.x * blockDim.x + threadIdx.x;
    if (e >= E) return;
    int d = dst[e];
    int pos = off_ptr()[d] + atomicAdd(&fill_ptr()[d], 1);
    ssrc_ptr()[pos] = src[e];
    sret_ptr()[pos] = et[e];
    sdst_ptr()[pos] = d;
}

// ---------------------------------------------------------------------------
// bf16 helpers: pack (x,y) into bf16x2 hi word + residual lo word.
// ---------------------------------------------------------------------------
__device__ __forceinline__ uint32_t bf2_split(float x, float y, uint32_t& lo_out) {
    __nv_bfloat162 h = __floats2bfloat162_rn(x, y);
    float2 hf = __bfloat1622float2(h);
    __nv_bfloat162 l = __floats2bfloat162_rn(x - hf.x, y - hf.y);
    lo_out = *reinterpret_cast<uint32_t*>(&l);
    return *reinterpret_cast<uint32_t*>(&h);
}

__device__ __forceinline__ void mma_bf16(float* c, const uint32_t* a, const uint32_t* b) {
    asm volatile(
        "mma.sync.aligned.m16n8k16.row.col.f32.bf16.bf16.f32 "
        "{%0,%1,%2,%3}, {%4,%5,%6,%7}, {%8,%9}, {%0,%1,%2,%3};"
        : "+f"(c[0]), "+f"(c[1]), "+f"(c[2]), "+f"(c[3])
        : "r"(a[0]), "r"(a[1]), "r"(a[2]), "r"(a[3]), "r"(b[0]), "r"(b[1]));
}

// ---------------------------------------------------------------------------
// Pre-split kernels: A rows -> packed uint2{hi,lo} pairs (32 per row).
// ---------------------------------------------------------------------------
__global__ void k_split_x(const float* __restrict__ x) {
    int i = blockIdx.x * blockDim.x + threadIdx.x;
    if (i >= N_NODES * 16) return;
    float4 v = reinterpret_cast<const float4*>(x)[i];
    uint32_t l01, l23;
    uint32_t h01 = bf2_split(v.x, v.y, l01);
    uint32_t h23 = bf2_split(v.z, v.w, l23);
    int row = i >> 4, c4 = i & 15;
    *reinterpret_cast<uint4*>(&axs_ptr()[(size_t)row * 32 + 2 * c4]) =
        make_uint4(h01, l01, h23, l23);
}

__global__ void k_split_h1() {
    int i = blockIdx.x * blockDim.x + threadIdx.x;
    if (i >= N_NODES * 16) return;
    float4 v = reinterpret_cast<const float4*>(g_h1)[i];
    v.x = fmaxf(v.x, 0.f); v.y = fmaxf(v.y, 0.f);
    v.z = fmaxf(v.z, 0.f); v.w = fmaxf(v.w, 0.f);
    uint32_t l01, l23;
    uint32_t h01 = bf2_split(v.x, v.y, l01);
    uint32_t h23 = bf2_split(v.z, v.w, l23);
    int row = i >> 4, c4 = i & 15;
    *reinterpret_cast<uint4*>(&axs_ptr()[(size_t)row * 32 + 2 * c4]) =
        make_uint4(h01, l01, h23, l23);
}

// ---------------------------------------------------------------------------
// Persistent fused GEMM body (A pre-split) — identical to R15-verified code.
// ---------------------------------------------------------------------------
namespace {
constexpr int SP = 36;
}

__device__ __forceinline__ void gemm_body(
    const uint2* __restrict__ Aps, const float* __restrict__ root,
    const float* __restrict__ W, const float* __restrict__ bias,
    float* __restrict__ outRoot, float* __restrict__ outWf,
    __half* __restrict__ outWh,
    int d1, int d2, int dout, int halfW, int rowBlocks) {
    __shared__ uint2 Ax[64 * SP];
    __shared__ uint2 Bx[64 * SP];

    const int tid = threadIdx.x;
    const int NC = (d1 + d2 + 63) / 64;
    const int cb = blockIdx.x % NC;
    const int seg = blockIdx.x / NC;
    const int dtot = d1 + d2;

#pragma unroll
    for (int i = 0; i < 8; ++i) {
        int idx = tid + i * 256;
        int p = idx >> 6, c = idx & 63;
        int gc = cb * 64 + c;
        int k0 = p * 2;
        float f0 = 0.f, f1 = 0.f;
        if (gc < d1) {
            f0 = root[(size_t)k0 * d1 + gc];
            f1 = root[(size_t)(k0 + 1) * d1 + gc];
        } else if (gc < dtot) {
            int w = gc - d1;
            int r = w / dout, j = w - r * dout;
            f0 = W[((size_t)r * 64 + k0) * dout + j];
            f1 = W[((size_t)r * 64 + k0 + 1) * dout + j];
        }
        uint32_t lo;
        uint32_t hi = bf2_split(f0, f1, lo);
        Bx[c * SP + p] = make_uint2(hi, lo);
    }

    const int wid = tid >> 5, lane = tid & 31;
    const int g = lane >> 2, tg = lane & 3;
    const int wm = (wid & 3) * 16;
    const int wn = (wid >> 2) * 32;
    const int arow = tid >> 4, ac4 = tid & 15;

    uint4 pref[4];
    {
        int rb = seg;
#pragma unroll
        for (int i = 0; i < 4; ++i) {
            int grow = rb * 64 + arow + i * 16;
            pref[i] = make_uint4(0u, 0u, 0u, 0u);
            if (rb < rowBlocks && grow < N_NODES)
                pref[i] = *reinterpret_cast<const uint4*>(
                    &Aps[(size_t)grow * 32 + 2 * ac4]);
        }
    }

    for (int rb = seg; rb < rowBlocks; rb += SEGS) {
#pragma unroll
        for (int i = 0; i < 4; ++i)
            *reinterpret_cast<uint4*>(&Ax[(arow + i * 16) * SP + 2 * ac4]) = pref[i];
        __syncthreads();

        {
            int rbn = rb + SEGS;
#pragma unroll
            for (int i = 0; i < 4; ++i) {
                int grow = rbn * 64 + arow + i * 16;
                uint4 v = make_uint4(0u, 0u, 0u, 0u);
                if (rbn < rowBlocks && grow < N_NODES)
                    v = *reinterpret_cast<const uint4*>(
                        &Aps[(size_t)grow * 32 + 2 * ac4]);
                pref[i] = v;
            }
        }

        float acc[4][4];
#pragma unroll
        for (int nt = 0; nt < 4; ++nt)
#pragma unroll
            for (int q = 0; q < 4; ++q) acc[nt][q] = 0.f;

#pragma unroll
        for (int ks = 0; ks < 4; ++ks) {
            const int p0 = ks * 8;
            uint2 A0 = Ax[(wm + g)     * SP + p0 + tg];
            uint2 A1 = Ax[(wm + g + 8) * SP + p0 + tg];
            uint2 A2 = Ax[(wm + g)     * SP + p0 + tg + 4];
            uint2 A3 = Ax[(wm + g + 8) * SP + p0 + tg + 4];
            uint32_t ah[4] = {A0.x, A1.x, A2.x, A3.x};
            uint32_t al[4] = {A0.y, A1.y, A2.y, A3.y};
            uint32_t bh[4][2], bl[4][2];
#pragma unroll
            for (int nt = 0; nt < 4; ++nt) {
                int c0 = wn + nt * 8 + g;
                uint2 B0 = Bx[c0 * SP + p0 + tg];
                uint2 B1 = Bx[c0 * SP + p0 + tg + 4];
                bh[nt][0] = B0.x; bh[nt][1] = B1.x;
                bl[nt][0] = B0.y; bl[nt][1] = B1.y;
            }
#pragma unroll
            for (int nt = 0; nt < 4; ++nt) {
                mma_bf16(acc[nt], ah, bh[nt]);
                mma_bf16(acc[nt], ah, bl[nt]);
                mma_bf16(acc[nt], al, bh[nt]);
            }
        }

#pragma unroll
        for (int nt = 0; nt < 4; ++nt) {
            int col = wn + nt * 8 + 2 * tg;
            int gc = cb * 64 + col;
            int r0 = rb * 64 + wm + g;
            int r1 = r0 + 8;
            float2 v0 = make_float2(acc[nt][0], acc[nt][1]);
            float2 v1 = make_float2(acc[nt][2], acc[nt][3]);
            if (gc < d1) {
                float bx = bias[gc], by = bias[gc + 1];
                v0.x += bx; v0.y += by; v1.x += bx; v1.y += by;
                if (r0 < N_NODES)
                    *reinterpret_cast<float2*>(&outRoot[(size_t)r0 * d1 + gc]) = v0;
                if (r1 < N_NODES)
                    *reinterpret_cast<float2*>(&outRoot[(size_t)r1 * d1 + gc]) = v1;
            } else if (gc < dtot) {
                int w = gc - d1;
                if (halfW) {
                    if (r0 < N_NODES)
                        *reinterpret_cast<__half2*>(&outWh[(size_t)r0 * d2 + w]) =
                            __floats2half2_rn(v0.x, v0.y);
                    if (r1 < N_NODES)
                        *reinterpret_cast<__half2*>(&outWh[(size_t)r1 * d2 + w]) =
                            __floats2half2_rn(v1.x, v1.y);
                } else {
                    if (r0 < N_NODES)
                        *reinterpret_cast<float2*>(&outWf[(size_t)r0 * d2 + w]) = v0;
                    if (r1 < N_NODES)
                        *reinterpret_cast<float2*>(&outWf[(size_t)r1 * d2 + w]) = v1;
                }
            }
        }
        __syncthreads();
    }
}

__global__ void __launch_bounds__(256) k_gemm_l1(
    const float* __restrict__ W1, const float* __restrict__ root1,
    const float* __restrict__ b1, int rowBlocks) {
    gemm_body(axs_ptr(), root1, W1, b1, g_h1, nullptr,
              reinterpret_cast<__half*>(g_agg), 64, 1024, 64, 1, rowBlocks);
}

__global__ void __launch_bounds__(256) k_gemm_l2(
    const float* __restrict__ W2, const float* __restrict__ root2,
    const float* __restrict__ b2, int rowBlocks) {
    gemm_body(axs_ptr(), root2, W2, b2, reinterpret_cast<float*>(g_cnt),
              g_agg, nullptr, 16, 256, 16, 0, rowBlocks);
}

// ---------------------------------------------------------------------------
__device__ __forceinline__ void red_add_v4(float* addr, float4 v) {
    asm volatile("red.global.add.v4.f32 [%0], {%1, %2, %3, %4};"
                 :: "l"(addr), "f"(v.x), "f"(v.y), "f"(v.z), "f"(v.w)
                 : "memory");
}

// Run-compacted scatter 1: thread = (16-edge sorted chunk, 8-col slice).
// Accumulate w*msg in registers while dst unchanged; RED once per dst-run.
__global__ void k_scat1(int E) {
    int gid = blockIdx.x * blockDim.x + threadIdx.x;
    int c = gid >> 3, lane = gid & 7;
    int base = c * CH;
    if (base >= E) return;
    int end = base + CH; if (end > E) end = E;
    const __half* xwh = reinterpret_cast<const __half*>(g_agg);
    float4 a0 = make_float4(0.f, 0.f, 0.f, 0.f);
    float4 a1 = make_float4(0.f, 0.f, 0.f, 0.f);
    int curd = sdst_ptr()[base];
    for (int i = base; i < end; ++i) {
        int d = sdst_ptr()[i];
        if (d != curd) {
            float* hp = &g_h1[(size_t)curd * D + lane * 8];
            red_add_v4(hp, a0);
            red_add_v4(hp + 4, a1);
            a0 = make_float4(0.f, 0.f, 0.f, 0.f);
            a1 = make_float4(0.f, 0.f, 0.f, 0.f);
            curd = d;
        }
        int s = ssrc_ptr()[i];
        int r = sret_ptr()[i];
        float w = g_inv[r * N_NODES + curd];
        uint4 raw = *reinterpret_cast<const uint4*>(
            &xwh[(size_t)s * 1024 + r * 64 + lane * 8]);
        float2 f0 = __half22float2(*reinterpret_cast<__half2*>(&raw.x));
        float2 f1 = __half22float2(*reinterpret_cast<__half2*>(&raw.y));
        float2 f2 = __half22float2(*reinterpret_cast<__half2*>(&raw.z));
        float2 f3 = __half22float2(*reinterpret_cast<__half2*>(&raw.w));
        a0.x += w * f0.x; a0.y += w * f0.y; a0.z += w * f1.x; a0.w += w * f1.y;
        a1.x += w * f2.x; a1.y += w * f2.y; a1.z += w * f3.x; a1.w += w * f3.y;
    }
    float* hp = &g_h1[(size_t)curd * D + lane * 8];
    red_add_v4(hp, a0);
    red_add_v4(hp + 4, a1);
}

// Run-compacted scatter 2: thread = (16-edge sorted chunk, 4-col slice).
__global__ void k_scat2(int E) {
    int gid = blockIdx.x * blockDim.x + threadIdx.x;
    int c = gid >> 2, q = gid & 3;
    int base = c * CH;
    if (base >= E) return;
    int end = base + CH; if (end > E) end = E;
    float4 acc = make_float4(0.f, 0.f, 0.f, 0.f);
    int curd = sdst_ptr()[base];
    float* oacc = reinterpret_cast<float*>(g_cnt);
    for (int i = base; i < end; ++i) {
        int d = sdst_ptr()[i];
        if (d != curd) {
            red_add_v4(&oacc[(size_t)curd * 16 + q * 4], acc);
            acc = make_float4(0.f, 0.f, 0.f, 0.f);
            curd = d;
        }
        int s = ssrc_ptr()[i];
        int r = sret_ptr()[i];
        float w = g_inv[r * N_NODES + curd];
        float4 v = *reinterpret_cast<const float4*>(
            &g_agg[(size_t)s * 256 + r * 16 + q * 4]);
        acc.x += w * v.x; acc.y += w * v.y;
        acc.z += w * v.z; acc.w += w * v.w;
    }
    red_add_v4(&oacc[(size_t)curd * 16 + q * 4], acc);
}

// relu + log_softmax over 16 classes; reads oacc (g_cnt storage), writes d_out
// with plain stores only. One thread per row.
__global__ void k_final(float* __restrict__ out) {
    int row = blockIdx.x * blockDim.x + threadIdx.x;
    if (row >= N_NODES) return;
    float v[16];
    const float4* p = reinterpret_cast<const float4*>(
        &reinterpret_cast<const float*>(g_cnt)[(size_t)row * 16]);
#pragma unroll
    for (int q = 0; q < 4; ++q) {
        float4 t = p[q];
        v[q * 4 + 0] = fmaxf(t.x, 0.f);
        v[q * 4 + 1] = fmaxf(t.y, 0.f);
        v[q * 4 + 2] = fmaxf(t.z, 0.f);
        v[q * 4 + 3] = fmaxf(t.w, 0.f);
    }
    float m = -1e30f;
#pragma unroll
    for (int j = 0; j < 16; ++j) m = fmaxf(m, v[j]);
    float s = 0.f;
#pragma unroll
    for (int j = 0; j < 16; ++j) s += expf(v[j] - m);
    float ls = m + logf(s);
    float4* q4 = reinterpret_cast<float4*>(&out[(size_t)row * 16]);
#pragma unroll
    for (int q = 0; q < 4; ++q)
        q4[q] = make_float4(v[q * 4 + 0] - ls, v[q * 4 + 1] - ls,
                            v[q * 4 + 2] - ls, v[q * 4 + 3] - ls);
}

// ---------------------------------------------------------------------------
extern "C" void kernel_launch(void* const* d_in, const int* in_sizes, int n_in,
                              void* d_out, int out_size) {
    const float* x     = (const float*)d_in[0];
    const int*   ei    = (const int*)d_in[1];
    const int*   et    = (const int*)d_in[2];
    const float* W1    = (const float*)d_in[3];
    const float* root1 = (const float*)d_in[4];
    const float* b1    = (const float*)d_in[5];
    const float* W2    = (const float*)d_in[6];
    const float* root2 = (const float*)d_in[7];
    const float* b2    = (const float*)d_in[8];
    float* out = (float*)d_out;

    const int E = in_sizes[2];
    const int* src = ei;
    const int* dst = ei + E;

    const int t = 256;
    const int gRN = (R * N_NODES + t - 1) / t;
    const int gN  = (N_NODES + t - 1) / t;
    const int gE  = (E + t - 1) / t;
    const int rowBlocks = (N_NODES + 63) / 64;
    const int gSplit = (N_NODES * 16 + t - 1) / t;
    const int scanBlocks = (N_NODES + 255) / 256;   // 391
    const int nCh = (E + CH - 1) / CH;
    const int gSc1 = (int)(((long long)nCh * 8 + t - 1) / t);
    const int gSc2 = (int)(((long long)nCh * 4 + t - 1) / t);

    // per-(r,dst) counts + inverse (g_cnt is dead after k_inv)
    k_zero_cnt<<<gRN, t>>>();
    k_count<<<gE, t>>>(dst, et, E);
    k_inv<<<gRN, t>>>();

    // dst counting sort -> sorted triples (reused by both layers)
    k_zero_dst<<<gN, t>>>();
    k_count_dst<<<gE, t>>>(dst, E);
    k_scan1<<<scanBlocks, 256>>>();
    k_scan2<<<1, 512>>>(scanBlocks);
    k_scan3<<<gN, t>>>();
    k_place<<<gE, t>>>(src, dst, et, E);

    // layer 1: pre-split x, GEMM, run-compacted scatter into h1
    k_split_x<<<gSplit, t>>>(x);
    k_gemm_l1<<<17 * SEGS, t>>>(W1, root1, b1, rowBlocks);
    k_scat1<<<gSc1, t>>>(E);

    // layer 2: pre-split relu(h1), GEMM (oacc in g_cnt, hw fp32), scatter, final
    k_split_h1<<<gSplit, t>>>();
    k_gemm_l2<<<5 * SEGS, t>>>(W2, root2, b2, rowBlocks);
    k_scat2<<<gSc2, t>>>(E);
    k_final<<<gN, t>>>(out);
}